// round 3
// baseline (speedup 1.0000x reference)
#include <cuda_runtime.h>
#include <stdint.h>
#include <math.h>

// Problem constants
constexpr int B  = 2;
constexpr int S  = 2048;
constexpr int D  = 1024;
constexpr int H  = 16;
constexpr int HD = 64;
constexpr int M  = B * S;   // 4096

// Scratch (device globals — no allocation allowed)
__device__ float g_q[(size_t)B * H * S * HD];
__device__ float g_k[(size_t)B * H * S * HD];
__device__ float g_v[(size_t)B * H * S * HD];
__device__ float g_attn[(size_t)B * S * D];

__device__ __forceinline__ uint32_t f2tf(float f) {
    uint32_t u;
    asm("cvt.rna.tf32.f32 %0, %1;" : "=r"(u) : "f"(f));
    return u;
}

__device__ __forceinline__ void mma8(float* c,
                                     uint32_t a0, uint32_t a1, uint32_t a2, uint32_t a3,
                                     uint32_t b0, uint32_t b1) {
    asm volatile(
        "mma.sync.aligned.m16n8k8.row.col.f32.tf32.tf32.f32 "
        "{%0,%1,%2,%3},{%4,%5,%6,%7},{%8,%9},{%0,%1,%2,%3};"
        : "+f"(c[0]), "+f"(c[1]), "+f"(c[2]), "+f"(c[3])
        : "r"(a0), "r"(a1), "r"(a2), "r"(a3), "r"(b0), "r"(b1));
}

// Fragment-major shared layouts:
//   A-tile (m16 x k8): 32 chunks of 4 regs; chunk index cs = lane ^ (lane>>3),
//     regs [ (m,kc), (m+8,kc), (m,kc+4), (m+8,kc+4) ]; tile stride 132.
//     element (m16,k8): lane=(m&7)*4+(k&3), reg=(m>>3)+2*((k>>2)&1).
//   B-tile (n8 x k8): 32 chunks of 2 regs; tile stride 66.
//     element (n8,k8): lane=(n&7)*4+(k&3), reg=(k>>2)&1.
#define CSWZ(l) ((l) ^ ((l) >> 3))

// ---------------------------------------------------------------------------
// TF32 tensor-core GEMM: C = A[M,1024] * W[1024,1024]^T + bias
// Block 128x128, BK=16, 8 warps, warp tile 64x32 (4x4 m16n8k8 tiles).
// MODE 0: row-major out. MODE 2: QKV fused, scatter to [B,H,S,HD].
// ---------------------------------------------------------------------------
template <int MODE>
__global__ __launch_bounds__(256)
void gemm_tc(const float* __restrict__ A,
             const float* __restrict__ W0, const float* __restrict__ b0_,
             const float* __restrict__ W1, const float* __restrict__ b1_,
             const float* __restrict__ W2, const float* __restrict__ b2_,
             float* __restrict__ C0, float* __restrict__ C1, float* __restrict__ C2)
{
    constexpr int K   = 1024;
    constexpr int N   = 1024;
    constexpr int NKB = K / 16;
    constexpr int ABUF = 16 * 132;   // 16 A-tiles per buffer
    constexpr int BBUF = 32 * 66;    // 32 B-tiles per buffer

    const float* W; const float* bias; float* C;
    if (MODE != 2) { W = W0; bias = b0_; C = C0; }
    else {
        const int z = blockIdx.z;
        W    = (z == 0) ? W0 : (z == 1) ? W1 : W2;
        bias = (z == 0) ? b0_ : (z == 1) ? b1_ : b2_;
        C    = (z == 0) ? C0 : (z == 1) ? C1 : C2;
    }

    extern __shared__ uint32_t smg[];
    uint32_t* As = smg;               // [2][ABUF]
    uint32_t* Bs = smg + 2 * ABUF;    // [2][BBUF]

    const int t    = threadIdx.x;
    const int lane = t & 31;
    const int warp = t >> 5;
    const int gid  = lane >> 2;
    const int tig  = lane & 3;
    const int wm   = warp >> 2;
    const int wn   = warp & 3;
    const int bm   = blockIdx.y * 128;
    const int bn   = blockIdx.x * 128;
    const int cs4  = CSWZ(lane) * 4;
    const int cs2  = CSWZ(lane) * 2;

    // staging assignment: row r = t&127, k-half ksh = t>>7
    const int rA   = t & 127;
    const int ksh  = t >> 7;
    const int mt8  = rA >> 4;
    const int nt16 = rA >> 3;
    const int halfA = (rA >> 3) & 1;
    const int gA   = rA & 7;
    const int aoff = (ksh * 8 + mt8) * 132;
    const int boff = (ksh * 16 + nt16) * 66;
    const float* Ap = A + (size_t)(bm + rA) * K + ksh * 8;
    const float* Wp = W + (size_t)(bn + rA) * K + ksh * 8;

    float4 pa0, pa1, pb0, pb1;
#define LDG_TILE(kb)                              \
    {                                             \
        const float* ap = Ap + (kb) * 16;         \
        const float* wp = Wp + (kb) * 16;         \
        pa0 = *(const float4*)ap;                 \
        pa1 = *(const float4*)(ap + 4);           \
        pb0 = *(const float4*)wp;                 \
        pb1 = *(const float4*)(wp + 4);           \
    }
#define STS_TILE(buf)                                                        \
    {                                                                        \
        uint32_t* ab = As + (buf) * ABUF + aoff + halfA;                     \
        uint32_t* bb = Bs + (buf) * BBUF + boff;                             \
        const float a0v[4] = {pa0.x, pa0.y, pa0.z, pa0.w};                   \
        const float a1v[4] = {pa1.x, pa1.y, pa1.z, pa1.w};                   \
        const float b0v[4] = {pb0.x, pb0.y, pb0.z, pb0.w};                   \
        const float b1v[4] = {pb1.x, pb1.y, pb1.z, pb1.w};                   \
        _Pragma("unroll")                                                    \
        for (int j = 0; j < 4; j++) {                                        \
            const int ln = gA * 4 + j;                                       \
            const int c  = CSWZ(ln);                                         \
            ab[c * 4 + 0] = f2tf(a0v[j]);                                    \
            ab[c * 4 + 2] = f2tf(a1v[j]);                                    \
            bb[c * 2 + 0] = f2tf(b0v[j]);                                    \
            bb[c * 2 + 1] = f2tf(b1v[j]);                                    \
        }                                                                    \
    }

    float acc[4][4][4];
#pragma unroll
    for (int i = 0; i < 4; i++)
#pragma unroll
        for (int j = 0; j < 4; j++)
#pragma unroll
            for (int l = 0; l < 4; l++) acc[i][j][l] = 0.f;

    LDG_TILE(0);
    STS_TILE(0);
    __syncthreads();

    for (int kb = 0; kb < NKB; kb++) {
        if (kb + 1 < NKB) LDG_TILE(kb + 1);
        const uint32_t* Ab = As + (kb & 1) * ABUF;
        const uint32_t* Bb = Bs + (kb & 1) * BBUF;
#pragma unroll
        for (int ks = 0; ks < 2; ks++) {
            uint4 af[4];
            uint2 bf[4];
#pragma unroll
            for (int mt = 0; mt < 4; mt++)
                af[mt] = *(const uint4*)&Ab[(ks * 8 + wm * 4 + mt) * 132 + cs4];
#pragma unroll
            for (int nt = 0; nt < 4; nt++)
                bf[nt] = *(const uint2*)&Bb[(ks * 16 + wn * 4 + nt) * 66 + cs2];
#pragma unroll
            for (int mt = 0; mt < 4; mt++)
#pragma unroll
                for (int nt = 0; nt < 4; nt++)
                    mma8(acc[mt][nt], af[mt].x, af[mt].y, af[mt].z, af[mt].w,
                         bf[nt].x, bf[nt].y);
        }
        if (kb + 1 < NKB) STS_TILE((kb + 1) & 1);
        __syncthreads();
    }

    // epilogue
#pragma unroll
    for (int mt = 0; mt < 4; mt++) {
        const int r1 = bm + wm * 64 + mt * 16 + gid;
        const int r2 = r1 + 8;
#pragma unroll
        for (int nt = 0; nt < 4; nt++) {
            const int n = bn + wn * 32 + nt * 8 + 2 * tig;
            const float bx = __ldg(&bias[n]), by = __ldg(&bias[n + 1]);
            float2 v1 = make_float2(acc[mt][nt][0] + bx, acc[mt][nt][1] + by);
            float2 v2 = make_float2(acc[mt][nt][2] + bx, acc[mt][nt][3] + by);
            if (MODE == 0) {
                *(float2*)&C[(size_t)r1 * N + n] = v1;
                *(float2*)&C[(size_t)r2 * N + n] = v2;
            } else {
                const int hh = n >> 6, ee = n & 63;
                const int b1r = r1 >> 11, s1r = r1 & (S - 1);
                const int b2r = r2 >> 11, s2r = r2 & (S - 1);
                *(float2*)&C[(((size_t)b1r * H + hh) * S + s1r) * HD + ee] = v1;
                *(float2*)&C[(((size_t)b2r * H + hh) * S + s2r) * HD + ee] = v2;
            }
        }
    }
#undef LDG_TILE
#undef STS_TILE
}

// ---------------------------------------------------------------------------
// TF32 tensor-core flash attention, fragment-major shared layouts.
// CTA = 64 Q rows of one (b,h). 4 warps; warp owns one 16-row m-tile.
// ---------------------------------------------------------------------------
constexpr int KF_OFF = 0;            // 64 tiles (ks8 x nt8) * 66
constexpr int VF_OFF = 64 * 66;      // 64 tiles * 66
constexpr int QP_OFF = 2 * 64 * 66;  // 32 tiles * 132 (Q frags, reused as P frags)
constexpr int ATTN_SMEM_U32 = QP_OFF + 32 * 132;  // 12672 u32 = 50688 B

__global__ __launch_bounds__(128)
void attn_tc(const float* __restrict__ q,
             const float* __restrict__ k,
             const float* __restrict__ v,
             float* __restrict__ out)
{
    extern __shared__ uint32_t sma[];
    uint32_t* Kf = sma + KF_OFF;
    uint32_t* Vf = sma + VF_OFF;
    uint32_t* QP = sma + QP_OFF;

    const int t    = threadIdx.x;
    const int lane = t & 31;
    const int warp = t >> 5;
    const int gid  = lane >> 2;
    const int tig  = lane & 3;
    const int cs4  = CSWZ(lane) * 4;
    const int cs2  = CSWZ(lane) * 2;

    const int hb = blockIdx.y, bb = blockIdx.z;
    const int m0 = blockIdx.x * 64;
    const size_t base = ((size_t)bb * H + hb) * S * HD;

    // staging assignment: row rs = t&63, e-half = (t>>6)*32
    const int rs = t & 63;
    const int eh = (t >> 6) * 32;
    const int gS = rs & 7;

    // ---- Stage Q (x 1/8) into A-fragment layout, tiles (ks*4 + mt) ----
    {
        const int mt   = rs >> 4;
        const int half = (rs >> 3) & 1;
        const float* qp = q + base + (size_t)(m0 + rs) * HD + eh;
#pragma unroll
        for (int i = 0; i < 8; i++) {
            const int e = eh + i * 4;
            const float4 qv = *(const float4*)(qp + i * 4);
            const float qa[4] = {qv.x, qv.y, qv.z, qv.w};
            uint32_t* dst = &QP[((e >> 3) * 4 + mt) * 132 + half + 2 * ((e >> 2) & 1)];
#pragma unroll
            for (int j = 0; j < 4; j++)
                dst[CSWZ(gS * 4 + j) * 4] = f2tf(qa[j] * 0.125f);
        }
    }
    __syncthreads();

    // Hoist Q fragments to registers (QP region is then reused for P)
    uint4 qf[8];
#pragma unroll
    for (int ks = 0; ks < 8; ks++)
        qf[ks] = *(const uint4*)&QP[(ks * 4 + warp) * 132 + cs4];

    float m1 = -1e30f, m2 = -1e30f, l1 = 0.f, l2 = 0.f;
    float o[8][4];
#pragma unroll
    for (int nt = 0; nt < 8; nt++)
#pragma unroll
        for (int j = 0; j < 4; j++) o[nt][j] = 0.f;

    // P-write addressing (C-fragment -> A-fragment layout)
    const int lw0  = gid * 4 + ((2 * tig) & 3);
    const int pcs0 = CSWZ(lw0);
    const int pcs1 = pcs0 ^ 1;
    const int preg = 2 * (tig >> 1);

    for (int kt = 0; kt < S / 64; kt++) {
        const int n0 = kt * 64;
        // ---- Stage K (B-frag for scores) and V (B-frag for PV) ----
        {
            const float* kp = k + base + (size_t)(n0 + rs) * HD + eh;
            const float* vp = v + base + (size_t)(n0 + rs) * HD + eh;
            const int kbV  = (rs >> 2) & 1;     // V reg index (k = rs)
            const int ntK  = rs >> 3;           // K n-tile
            const int ksV  = rs >> 3;           // V k-tile
#pragma unroll
            for (int i = 0; i < 8; i++) {
                const int e = eh + i * 4;
                const float4 kv = *(const float4*)(kp + i * 4);
                const float ka[4] = {kv.x, kv.y, kv.z, kv.w};
                uint32_t* kd = &Kf[((e >> 3) * 8 + ntK) * 66 + ((e >> 2) & 1)];
#pragma unroll
                for (int j = 0; j < 4; j++)
                    kd[CSWZ(gS * 4 + j) * 2] = f2tf(ka[j]);

                const float4 vv = *(const float4*)(vp + i * 4);
                const float va[4] = {vv.x, vv.y, vv.z, vv.w};
                uint32_t* vd = &Vf[(ksV * 8 + (e >> 3)) * 66 + kbV];
#pragma unroll
                for (int j = 0; j < 4; j++)
                    vd[CSWZ(((e + j) & 7) * 4 + (rs & 3)) * 2] = f2tf(va[j]);
            }
        }
        __syncthreads();

        // ---- scores = Q . K^T ----
        float sc[8][4];
#pragma unroll
        for (int nt = 0; nt < 8; nt++)
#pragma unroll
            for (int j = 0; j < 4; j++) sc[nt][j] = 0.f;
#pragma unroll
        for (int ks = 0; ks < 8; ks++) {
#pragma unroll
            for (int nt = 0; nt < 8; nt++) {
                const uint2 bf = *(const uint2*)&Kf[(ks * 8 + nt) * 66 + cs2];
                mma8(sc[nt], qf[ks].x, qf[ks].y, qf[ks].z, qf[ks].w, bf.x, bf.y);
            }
        }

        // ---- online softmax in registers ----
        float mx1 = -1e30f, mx2 = -1e30f;
#pragma unroll
        for (int nt = 0; nt < 8; nt++) {
            mx1 = fmaxf(mx1, fmaxf(sc[nt][0], sc[nt][1]));
            mx2 = fmaxf(mx2, fmaxf(sc[nt][2], sc[nt][3]));
        }
        mx1 = fmaxf(mx1, __shfl_xor_sync(0xffffffffu, mx1, 1));
        mx1 = fmaxf(mx1, __shfl_xor_sync(0xffffffffu, mx1, 2));
        mx2 = fmaxf(mx2, __shfl_xor_sync(0xffffffffu, mx2, 1));
        mx2 = fmaxf(mx2, __shfl_xor_sync(0xffffffffu, mx2, 2));
        const float M1 = fmaxf(m1, mx1);
        const float M2 = fmaxf(m2, mx2);

        float s1 = 0.f, s2 = 0.f;
#pragma unroll
        for (int nt = 0; nt < 8; nt++) {
            sc[nt][0] = __expf(sc[nt][0] - M1); s1 += sc[nt][0];
            sc[nt][1] = __expf(sc[nt][1] - M1); s1 += sc[nt][1];
            sc[nt][2] = __expf(sc[nt][2] - M2); s2 += sc[nt][2];
            sc[nt][3] = __expf(sc[nt][3] - M2); s2 += sc[nt][3];
        }
        s1 += __shfl_xor_sync(0xffffffffu, s1, 1);
        s1 += __shfl_xor_sync(0xffffffffu, s1, 2);
        s2 += __shfl_xor_sync(0xffffffffu, s2, 1);
        s2 += __shfl_xor_sync(0xffffffffu, s2, 2);

        const float c1 = __expf(m1 - M1);
        const float c2 = __expf(m2 - M2);
        l1 = l1 * c1 + s1;
        l2 = l2 * c2 + s2;
        m1 = M1; m2 = M2;
#pragma unroll
        for (int nt = 0; nt < 8; nt++) {
            o[nt][0] *= c1; o[nt][1] *= c1;
            o[nt][2] *= c2; o[nt][3] *= c2;
        }

        // ---- P (C-frag) -> A-frag layout in warp-private region ----
#pragma unroll
        for (int nt = 0; nt < 8; nt++) {
            uint32_t* pb = &QP[(warp * 8 + nt) * 132];
            *(uint2*)&pb[pcs0 * 4 + preg] = make_uint2(f2tf(sc[nt][0]), f2tf(sc[nt][2]));
            *(uint2*)&pb[pcs1 * 4 + preg] = make_uint2(f2tf(sc[nt][1]), f2tf(sc[nt][3]));
        }
        __syncwarp();

        // ---- O += P . V ----
#pragma unroll
        for (int ksp = 0; ksp < 8; ksp++) {
            const uint4 pf = *(const uint4*)&QP[(warp * 8 + ksp) * 132 + cs4];
#pragma unroll
            for (int nt = 0; nt < 8; nt++) {
                const uint2 vb = *(const uint2*)&Vf[(ksp * 8 + nt) * 66 + cs2];
                mma8(o[nt], pf.x, pf.y, pf.z, pf.w, vb.x, vb.y);
            }
        }
        __syncthreads();
    }

    // ---- epilogue ----
    const float i1 = 1.f / l1;
    const float i2 = 1.f / l2;
    const int s1r = m0 + warp * 16 + gid;
    const int s2r = s1r + 8;
#pragma unroll
    for (int nt = 0; nt < 8; nt++) {
        const int n = nt * 8 + 2 * tig;
        *(float2*)&out[((size_t)bb * S + s1r) * D + hb * HD + n] =
            make_float2(o[nt][0] * i1, o[nt][1] * i1);
        *(float2*)&out[((size_t)bb * S + s2r) * D + hb * HD + n] =
            make_float2(o[nt][2] * i2, o[nt][3] * i2);
    }
}

// ---------------------------------------------------------------------------
// Launch
// ---------------------------------------------------------------------------
extern "C" void kernel_launch(void* const* d_in, const int* in_sizes, int n_in,
                              void* d_out, int out_size)
{
    const float* x  = (const float*)d_in[0];
    const float* Wq = (const float*)d_in[1];
    const float* bq = (const float*)d_in[2];
    const float* Wk = (const float*)d_in[3];
    const float* bk = (const float*)d_in[4];
    const float* Wv = (const float*)d_in[5];
    const float* bv = (const float*)d_in[6];
    const float* Wp = (const float*)d_in[7];
    const float* bp = (const float*)d_in[8];
    float* out = (float*)d_out;

    float *q, *k, *v, *attn;
    cudaGetSymbolAddress((void**)&q,    g_q);
    cudaGetSymbolAddress((void**)&k,    g_k);
    cudaGetSymbolAddress((void**)&v,    g_v);
    cudaGetSymbolAddress((void**)&attn, g_attn);

    const int smem_gemm = (2 * 16 * 132 + 2 * 32 * 66) * (int)sizeof(uint32_t); // 33792
    const int smem_attn = ATTN_SMEM_U32 * (int)sizeof(uint32_t);                // 50688

    cudaFuncSetAttribute(attn_tc, cudaFuncAttributeMaxDynamicSharedMemorySize, smem_attn);

    gemm_tc<2><<<dim3(D / 128, M / 128, 3), 256, smem_gemm>>>(
        x, Wq, bq, Wk, bk, Wv, bv, q, k, v);

    attn_tc<<<dim3(S / 64, H, B), 128, smem_attn>>>(q, k, v, attn);

    gemm_tc<0><<<dim3(D / 128, M / 128), 256, smem_gemm>>>(
        attn, Wp, bp, nullptr, nullptr, nullptr, nullptr, out, nullptr, nullptr);
}

// round 4
// speedup vs baseline: 1.0929x; 1.0929x over previous
#include <cuda_runtime.h>
#include <stdint.h>
#include <math.h>

// Problem constants
constexpr int B  = 2;
constexpr int S  = 2048;
constexpr int D  = 1024;
constexpr int H  = 16;
constexpr int HD = 64;
constexpr int M  = B * S;   // 4096

// Scratch (device globals — no allocation allowed)
__device__ float g_q[(size_t)B * H * S * HD];
__device__ float g_k[(size_t)B * H * S * HD];
__device__ float g_v[(size_t)B * H * S * HD];
__device__ float g_attn[(size_t)B * S * D];

__device__ __forceinline__ uint32_t f2tf(float f) {
    uint32_t u;
    asm("cvt.rna.tf32.f32 %0, %1;" : "=r"(u) : "f"(f));
    return u;
}

__device__ __forceinline__ void mma8(float* c,
                                     uint32_t a0, uint32_t a1, uint32_t a2, uint32_t a3,
                                     uint32_t b0, uint32_t b1) {
    asm volatile(
        "mma.sync.aligned.m16n8k8.row.col.f32.tf32.tf32.f32 "
        "{%0,%1,%2,%3},{%4,%5,%6,%7},{%8,%9},{%0,%1,%2,%3};"
        : "+f"(c[0]), "+f"(c[1]), "+f"(c[2]), "+f"(c[3])
        : "r"(a0), "r"(a1), "r"(a2), "r"(a3), "r"(b0), "r"(b1));
}

// ldmatrix x4: four 8x8 b16 matrices; per-lane shared address (16B row ptr).
__device__ __forceinline__ uint4 ldsm4(uint32_t addr) {
    uint4 r;
    asm volatile("ldmatrix.sync.aligned.m8n8.x4.shared.b16 {%0,%1,%2,%3}, [%4];"
                 : "=r"(r.x), "=r"(r.y), "=r"(r.z), "=r"(r.w) : "r"(addr));
    return r;
}

__device__ __forceinline__ uint4 cvt4(float4 v) {
    return make_uint4(f2tf(v.x), f2tf(v.y), f2tf(v.z), f2tf(v.w));
}

// ---------------------------------------------------------------------------
// TF32 tensor-core GEMM: C = A[M,1024] * W[1024,1024]^T + bias
// Block 128x128, BK=16, 8 warps, warp tile 64x32.
// Smem: row-major BK=16 with group swizzle g' = g ^ ((row>>1)&3).
// STS.128 staging; ldmatrix.x4 fragment loads.
// MODE 0: row-major out. MODE 2: QKV fused (blockIdx.z), scatter [B,H,S,HD].
// ---------------------------------------------------------------------------
template <int MODE>
__global__ __launch_bounds__(256)
void gemm_tc(const float* __restrict__ A,
             const float* __restrict__ W0, const float* __restrict__ b0_,
             const float* __restrict__ W1, const float* __restrict__ b1_,
             const float* __restrict__ W2, const float* __restrict__ b2_,
             float* __restrict__ C0, float* __restrict__ C1, float* __restrict__ C2)
{
    constexpr int K   = 1024;
    constexpr int N   = 1024;
    constexpr int NKB = K / 16;

    const float* W; const float* bias; float* C;
    if (MODE != 2) { W = W0; bias = b0_; C = C0; }
    else {
        const int z = blockIdx.z;
        W    = (z == 0) ? W0 : (z == 1) ? W1 : W2;
        bias = (z == 0) ? b0_ : (z == 1) ? b1_ : b2_;
        C    = (z == 0) ? C0 : (z == 1) ? C1 : C2;
    }

    // byte map: A buf0 @0, A buf1 @8192, B buf0 @16384, B buf1 @24576
    extern __shared__ __align__(16) uint32_t smg[];
    uint32_t* As = smg;           // words
    uint32_t* Bs = smg + 4096;
    const uint32_t sbase = (uint32_t)__cvta_generic_to_shared(smg);

    const int t    = threadIdx.x;
    const int lane = t & 31;
    const int warp = t >> 5;
    const int gid  = lane >> 2;
    const int tig  = lane & 3;
    const int wm   = warp >> 2;
    const int wn   = warp & 3;
    const int bm   = blockIdx.y * 128;
    const int bn   = blockIdx.x * 128;

    // ---- staging: thread handles rows rl and rl+64, k-group gl ----
    const int rl = t >> 2;        // 0..63
    const int gl = t & 3;
    const float* Ap0 = A + (size_t)(bm + rl) * K + gl * 4;
    const float* Ap1 = Ap0 + (size_t)64 * K;
    const float* Wp0 = W + (size_t)(bn + rl) * K + gl * 4;
    const float* Wp1 = Wp0 + (size_t)64 * K;
    const int wsts = rl * 16 + ((gl ^ ((rl >> 1) & 3)) << 2);   // word offset; rows+64 same swizzle

    // ---- fragment relative byte addrs (buffer 0; k-step via ^ (ks<<5)) ----
    uint32_t relA[4], relB[2];
    {
        const int hiA = (lane >> 4) & 1;
#pragma unroll
        for (int mt = 0; mt < 4; mt++) {
            const int row = wm * 64 + mt * 16 + (lane & 7) + (lane & 8);
            relA[mt] = row * 64 + (uint32_t)((hiA ^ ((row >> 1) & 3)) << 4);
        }
        const int hiB = (lane >> 3) & 1;
#pragma unroll
        for (int n2 = 0; n2 < 2; n2++) {
            const int row = wn * 32 + n2 * 16 + (lane & 7) + ((lane >> 1) & 8);
            relB[n2] = 16384u + row * 64 + (uint32_t)((hiB ^ ((row >> 1) & 3)) << 4);
        }
    }

    float4 pa0, pa1, pb0, pb1;
#define LDG_TILE(kb)                                   \
    {                                                  \
        pa0 = *(const float4*)(Ap0 + (kb) * 16);       \
        pa1 = *(const float4*)(Ap1 + (kb) * 16);       \
        pb0 = *(const float4*)(Wp0 + (kb) * 16);       \
        pb1 = *(const float4*)(Wp1 + (kb) * 16);       \
    }
#define STS_TILE(buf)                                  \
    {                                                  \
        uint32_t* a = As + (buf) * 2048 + wsts;        \
        uint32_t* b = Bs + (buf) * 2048 + wsts;        \
        *(uint4*)a          = cvt4(pa0);               \
        *(uint4*)(a + 1024) = cvt4(pa1);               \
        *(uint4*)b          = cvt4(pb0);               \
        *(uint4*)(b + 1024) = cvt4(pb1);               \
    }

    float acc[4][4][4];
#pragma unroll
    for (int i = 0; i < 4; i++)
#pragma unroll
        for (int j = 0; j < 4; j++)
#pragma unroll
            for (int l = 0; l < 4; l++) acc[i][j][l] = 0.f;

    LDG_TILE(0);
    STS_TILE(0);
    __syncthreads();

    for (int kb = 0; kb < NKB; kb++) {
        if (kb + 1 < NKB) LDG_TILE(kb + 1);
        const uint32_t sb_kb = sbase + (uint32_t)((kb & 1) << 13);
#pragma unroll
        for (int ks = 0; ks < 2; ks++) {
            const uint32_t kx = (uint32_t)(ks << 5);
            uint4 af[4];
#pragma unroll
            for (int mt = 0; mt < 4; mt++)
                af[mt] = ldsm4(sb_kb + (relA[mt] ^ kx));
            const uint4 bq0 = ldsm4(sb_kb + (relB[0] ^ kx));
            const uint4 bq1 = ldsm4(sb_kb + (relB[1] ^ kx));
#pragma unroll
            for (int mt = 0; mt < 4; mt++) {
                mma8(acc[mt][0], af[mt].x, af[mt].y, af[mt].z, af[mt].w, bq0.x, bq0.y);
                mma8(acc[mt][1], af[mt].x, af[mt].y, af[mt].z, af[mt].w, bq0.z, bq0.w);
                mma8(acc[mt][2], af[mt].x, af[mt].y, af[mt].z, af[mt].w, bq1.x, bq1.y);
                mma8(acc[mt][3], af[mt].x, af[mt].y, af[mt].z, af[mt].w, bq1.z, bq1.w);
            }
        }
        if (kb + 1 < NKB) STS_TILE((kb + 1) & 1);
        __syncthreads();
    }

    // ---- epilogue ----
#pragma unroll
    for (int mt = 0; mt < 4; mt++) {
        const int r1 = bm + wm * 64 + mt * 16 + gid;
        const int r2 = r1 + 8;
#pragma unroll
        for (int nt = 0; nt < 4; nt++) {
            const int n = bn + wn * 32 + nt * 8 + 2 * tig;
            const float bx = __ldg(&bias[n]), by = __ldg(&bias[n + 1]);
            float2 v1 = make_float2(acc[mt][nt][0] + bx, acc[mt][nt][1] + by);
            float2 v2 = make_float2(acc[mt][nt][2] + bx, acc[mt][nt][3] + by);
            if (MODE == 0) {
                *(float2*)&C[(size_t)r1 * N + n] = v1;
                *(float2*)&C[(size_t)r2 * N + n] = v2;
            } else {
                const int hh = n >> 6, ee = n & 63;
                const int b1r = r1 >> 11, s1r = r1 & (S - 1);
                const int b2r = r2 >> 11, s2r = r2 & (S - 1);
                *(float2*)&C[(((size_t)b1r * H + hh) * S + s1r) * HD + ee] = v1;
                *(float2*)&C[(((size_t)b2r * H + hh) * S + s2r) * HD + ee] = v2;
            }
        }
    }
#undef LDG_TILE
#undef STS_TILE
}

// ---------------------------------------------------------------------------
// TF32 tensor-core flash attention (R2 structure; K tile via swizzled
// row-major smem + ldmatrix.x4 B-fragment loads for the scores MMA).
// CTA = 64 Q rows of one (b,h). 4 warps; warp owns 16 Q rows.
// Smem words: Qs 64x68 | Ks 64x64 (swizzled) | Vs 64x72 | Ps 64x68
// ---------------------------------------------------------------------------
constexpr int QS_OFF = 0;
constexpr int KS_OFF = 64 * 68;            // 4352
constexpr int VS_OFF = KS_OFF + 64 * 64;   // 8448
constexpr int PS_OFF = VS_OFF + 64 * 72;   // 13056
constexpr int ATTN_SMEM_U32 = PS_OFF + 64 * 68;   // 17408 words = 69632 B

__global__ __launch_bounds__(128)
void attn_tc(const float* __restrict__ q,
             const float* __restrict__ k,
             const float* __restrict__ v,
             float* __restrict__ out)
{
    extern __shared__ __align__(16) uint32_t sma[];
    uint32_t* Qs = sma + QS_OFF;
    uint32_t* Ks = sma + KS_OFF;
    uint32_t* Vs = sma + VS_OFF;
    uint32_t* Ps = sma + PS_OFF;
    const uint32_t kbase = (uint32_t)__cvta_generic_to_shared(sma) + KS_OFF * 4;

    const int t    = threadIdx.x;
    const int lane = t & 31;
    const int warp = t >> 5;
    const int gid  = lane >> 2;
    const int tig  = lane & 3;
    const int rm   = warp * 16;

    const int hb = blockIdx.y, bb = blockIdx.z;
    const int m0 = blockIdx.x * 64;
    const size_t base = ((size_t)bb * H + hb) * S * HD;

    // ---- Stage Q (x 0.125) ----
#pragma unroll
    for (int i = 0; i < 8; i++) {
        const int f = t + i * 128;
        const int r = f >> 4, c = (f & 15) * 4;
        const float4 qv = *(const float4*)&q[base + (size_t)(m0 + r) * HD + c];
        uint32_t* p = &Qs[r * 68 + c];
        p[0] = f2tf(qv.x * 0.125f); p[1] = f2tf(qv.y * 0.125f);
        p[2] = f2tf(qv.z * 0.125f); p[3] = f2tf(qv.w * 0.125f);
    }
    __syncthreads();

    // Hoist Q fragments to registers
    uint4 qf[8];
#pragma unroll
    for (int ks = 0; ks < 8; ks++) {
        const int c = ks * 8 + tig;
        qf[ks].x = Qs[(rm + gid) * 68 + c];
        qf[ks].y = Qs[(rm + gid + 8) * 68 + c];
        qf[ks].z = Qs[(rm + gid) * 68 + c + 4];
        qf[ks].w = Qs[(rm + gid + 8) * 68 + c + 4];
    }

    // K B-fragment base addrs (4 x4-loads cover 8 n-tiles); k-step via ^(ks<<5)
    uint32_t relK[4];
    {
        const int hi = (lane >> 3) & 1;
#pragma unroll
        for (int n2 = 0; n2 < 4; n2++) {
            const int row = n2 * 16 + (lane & 7) + ((lane >> 1) & 8);
            relK[n2] = row * 256 + (uint32_t)((hi ^ (row & 7)) << 4);
        }
    }

    float m1 = -1e30f, m2 = -1e30f, l1 = 0.f, l2 = 0.f;
    float o[8][4];
#pragma unroll
    for (int nt = 0; nt < 8; nt++)
#pragma unroll
        for (int j = 0; j < 4; j++) o[nt][j] = 0.f;

    for (int kt = 0; kt < S / 64; kt++) {
        const int n0 = kt * 64;
        // ---- Stage K (swizzled row-major, STS.128) and V (R2 layout) ----
#pragma unroll
        for (int i = 0; i < 8; i++) {
            const int f = t + i * 128;
            const int r = f >> 4, g = f & 15, c = g * 4;
            const float4 kv = *(const float4*)&k[base + (size_t)(n0 + r) * HD + c];
            *(uint4*)&Ks[r * 64 + ((g ^ (r & 7)) << 2)] = cvt4(kv);
            const float4 vv = *(const float4*)&v[base + (size_t)(n0 + r) * HD + c];
            uint32_t* pv = &Vs[r * 72 + c];
            pv[0] = f2tf(vv.x); pv[1] = f2tf(vv.y); pv[2] = f2tf(vv.z); pv[3] = f2tf(vv.w);
        }
        __syncthreads();

        // ---- scores = Q . K^T via ldmatrix.x4 ----
        float sc[8][4];
#pragma unroll
        for (int nt = 0; nt < 8; nt++)
#pragma unroll
            for (int j = 0; j < 4; j++) sc[nt][j] = 0.f;
#pragma unroll
        for (int ks = 0; ks < 8; ks++) {
            const uint32_t kx = (uint32_t)(ks << 5);
#pragma unroll
            for (int n2 = 0; n2 < 4; n2++) {
                const uint4 bf = ldsm4(kbase + (relK[n2] ^ kx));
                mma8(sc[2 * n2],     qf[ks].x, qf[ks].y, qf[ks].z, qf[ks].w, bf.x, bf.y);
                mma8(sc[2 * n2 + 1], qf[ks].x, qf[ks].y, qf[ks].z, qf[ks].w, bf.z, bf.w);
            }
        }

        // ---- online softmax in registers ----
        float mx1 = -1e30f, mx2 = -1e30f;
#pragma unroll
        for (int nt = 0; nt < 8; nt++) {
            mx1 = fmaxf(mx1, fmaxf(sc[nt][0], sc[nt][1]));
            mx2 = fmaxf(mx2, fmaxf(sc[nt][2], sc[nt][3]));
        }
        mx1 = fmaxf(mx1, __shfl_xor_sync(0xffffffffu, mx1, 1));
        mx1 = fmaxf(mx1, __shfl_xor_sync(0xffffffffu, mx1, 2));
        mx2 = fmaxf(mx2, __shfl_xor_sync(0xffffffffu, mx2, 1));
        mx2 = fmaxf(mx2, __shfl_xor_sync(0xffffffffu, mx2, 2));
        const float M1 = fmaxf(m1, mx1);
        const float M2 = fmaxf(m2, mx2);

        float s1 = 0.f, s2 = 0.f;
#pragma unroll
        for (int nt = 0; nt < 8; nt++) {
            sc[nt][0] = __expf(sc[nt][0] - M1); s1 += sc[nt][0];
            sc[nt][1] = __expf(sc[nt][1] - M1); s1 += sc[nt][1];
            sc[nt][2] = __expf(sc[nt][2] - M2); s2 += sc[nt][2];
            sc[nt][3] = __expf(sc[nt][3] - M2); s2 += sc[nt][3];
        }
        s1 += __shfl_xor_sync(0xffffffffu, s1, 1);
        s1 += __shfl_xor_sync(0xffffffffu, s1, 2);
        s2 += __shfl_xor_sync(0xffffffffu, s2, 1);
        s2 += __shfl_xor_sync(0xffffffffu, s2, 2);

        const float c1 = __expf(m1 - M1);
        const float c2 = __expf(m2 - M2);
        l1 = l1 * c1 + s1;
        l2 = l2 * c2 + s2;
        m1 = M1; m2 = M2;
#pragma unroll
        for (int nt = 0; nt < 8; nt++) {
            o[nt][0] *= c1; o[nt][1] *= c1;
            o[nt][2] *= c2; o[nt][3] *= c2;
        }

        // ---- P -> smem (tf32), warp-private rows ----
#pragma unroll
        for (int nt = 0; nt < 8; nt++) {
            const int cc = nt * 8 + 2 * tig;
            *(uint2*)&Ps[(rm + gid) * 68 + cc]     = make_uint2(f2tf(sc[nt][0]), f2tf(sc[nt][1]));
            *(uint2*)&Ps[(rm + gid + 8) * 68 + cc] = make_uint2(f2tf(sc[nt][2]), f2tf(sc[nt][3]));
        }
        __syncwarp();

        // ---- O += P . V ----
#pragma unroll
        for (int ksp = 0; ksp < 8; ksp++) {
            const int c = ksp * 8 + tig;
            const uint32_t pa0 = Ps[(rm + gid) * 68 + c];
            const uint32_t pa1 = Ps[(rm + gid + 8) * 68 + c];
            const uint32_t pa2 = Ps[(rm + gid) * 68 + c + 4];
            const uint32_t pa3 = Ps[(rm + gid + 8) * 68 + c + 4];
#pragma unroll
            for (int nt = 0; nt < 8; nt++) {
                const uint32_t vb0 = Vs[(ksp * 8 + tig) * 72 + nt * 8 + gid];
                const uint32_t vb1 = Vs[(ksp * 8 + tig + 4) * 72 + nt * 8 + gid];
                mma8(o[nt], pa0, pa1, pa2, pa3, vb0, vb1);
            }
        }
        __syncthreads();
    }

    // ---- epilogue ----
    const float i1 = 1.f / l1;
    const float i2 = 1.f / l2;
    const int s1r = m0 + rm + gid;
    const int s2r = s1r + 8;
#pragma unroll
    for (int nt = 0; nt < 8; nt++) {
        const int n = nt * 8 + 2 * tig;
        *(float2*)&out[((size_t)bb * S + s1r) * D + hb * HD + n] =
            make_float2(o[nt][0] * i1, o[nt][1] * i1);
        *(float2*)&out[((size_t)bb * S + s2r) * D + hb * HD + n] =
            make_float2(o[nt][2] * i2, o[nt][3] * i2);
    }
}

// ---------------------------------------------------------------------------
// Launch
// ---------------------------------------------------------------------------
extern "C" void kernel_launch(void* const* d_in, const int* in_sizes, int n_in,
                              void* d_out, int out_size)
{
    const float* x  = (const float*)d_in[0];
    const float* Wq = (const float*)d_in[1];
    const float* bq = (const float*)d_in[2];
    const float* Wk = (const float*)d_in[3];
    const float* bk = (const float*)d_in[4];
    const float* Wv = (const float*)d_in[5];
    const float* bv = (const float*)d_in[6];
    const float* Wp = (const float*)d_in[7];
    const float* bp = (const float*)d_in[8];
    float* out = (float*)d_out;

    float *q, *k, *v, *attn;
    cudaGetSymbolAddress((void**)&q,    g_q);
    cudaGetSymbolAddress((void**)&k,    g_k);
    cudaGetSymbolAddress((void**)&v,    g_v);
    cudaGetSymbolAddress((void**)&attn, g_attn);

    const int smem_gemm = 32768;                                  // 2x(A+B) buffers
    const int smem_attn = ATTN_SMEM_U32 * (int)sizeof(uint32_t);  // 69632

    cudaFuncSetAttribute(attn_tc, cudaFuncAttributeMaxDynamicSharedMemorySize, smem_attn);

    gemm_tc<2><<<dim3(D / 128, M / 128, 3), 256, smem_gemm>>>(
        x, Wq, bq, Wk, bk, Wv, bv, q, k, v);

    attn_tc<<<dim3(S / 64, H, B), 128, smem_attn>>>(q, k, v, attn);

    gemm_tc<0><<<dim3(D / 128, M / 128), 256, smem_gemm>>>(
        attn, Wp, bp, nullptr, nullptr, nullptr, nullptr, out, nullptr, nullptr);
}

// round 8
// speedup vs baseline: 2.2807x; 2.0869x over previous
#include <cuda_runtime.h>
#include <stdint.h>

constexpr int B  = 2;
constexpr int S  = 2048;
constexpr int D  = 1024;
constexpr int H  = 16;
constexpr int HD = 64;
constexpr int M  = B * S;   // 4096

// Scratch (device globals — no allocation allowed)
__device__ float g_q[(size_t)B * H * S * HD];
__device__ float g_k[(size_t)B * H * S * HD];
__device__ float g_v[(size_t)B * H * S * HD];
__device__ float g_attn[(size_t)B * S * D];
__device__ float g_xt[(size_t)M * D];          // tf32-rounded x
__device__ float g_wt[4 * (size_t)D * D];      // tf32-rounded Wq,Wk,Wv,Wp

__device__ __forceinline__ uint32_t f2tf(float f) {
    uint32_t u;
    asm("cvt.rna.tf32.f32 %0, %1;" : "=r"(u) : "f"(f));
    return u;
}
__device__ __forceinline__ float rndtf(float f) { return __uint_as_float(f2tf(f)); }

__device__ __forceinline__ void mma8(float* c,
                                     uint32_t a0, uint32_t a1, uint32_t a2, uint32_t a3,
                                     uint32_t b0, uint32_t b1) {
    asm volatile(
        "mma.sync.aligned.m16n8k8.row.col.f32.tf32.tf32.f32 "
        "{%0,%1,%2,%3},{%4,%5,%6,%7},{%8,%9},{%0,%1,%2,%3};"
        : "+f"(c[0]), "+f"(c[1]), "+f"(c[2]), "+f"(c[3])
        : "r"(a0), "r"(a1), "r"(a2), "r"(a3), "r"(b0), "r"(b1));
}

__device__ __forceinline__ uint4 ldsm4(uint32_t addr) {
    uint4 r;
    asm volatile("ldmatrix.sync.aligned.m8n8.x4.shared.b16 {%0,%1,%2,%3}, [%4];"
                 : "=r"(r.x), "=r"(r.y), "=r"(r.z), "=r"(r.w) : "r"(addr));
    return r;
}

__device__ __forceinline__ void cpa16(uint32_t dst, const void* src) {
    asm volatile("cp.async.cg.shared.global [%0], [%1], 16;" :: "r"(dst), "l"(src));
}
__device__ __forceinline__ void cpcommit() { asm volatile("cp.async.commit_group;"); }
template <int N>
__device__ __forceinline__ void cpwait() { asm volatile("cp.async.wait_group %0;" :: "n"(N)); }

// ---------------------------------------------------------------------------
// tf32 pre-round pass: x and the 4 weight matrices
// ---------------------------------------------------------------------------
__global__ __launch_bounds__(256)
void tf32_cvt(const float* __restrict__ x,  const float* __restrict__ wq,
              const float* __restrict__ wk, const float* __restrict__ wv,
              const float* __restrict__ wp,
              float* __restrict__ xo, float* __restrict__ qo,
              float* __restrict__ ko, float* __restrict__ vo, float* __restrict__ po)
{
    const float* s; float* d; int n;
    switch (blockIdx.y) {
        case 0: s = x;  d = xo; n = M * D; break;
        case 1: s = wq; d = qo; n = D * D; break;
        case 2: s = wk; d = ko; n = D * D; break;
        case 3: s = wv; d = vo; n = D * D; break;
        default: s = wp; d = po; n = D * D; break;
    }
    for (int i = (blockIdx.x * 256 + threadIdx.x) * 4; i < n; i += 512 * 256 * 4) {
        const float4 v = *(const float4*)(s + i);
        *(uint4*)(d + i) = make_uint4(f2tf(v.x), f2tf(v.y), f2tf(v.z), f2tf(v.w));
    }
}

// ---------------------------------------------------------------------------
// TF32 GEMM: C = A[M,1024] * W[1024,1024]^T + bias.  Inputs pre-rounded.
// Block 128x128, BK=16, 8 warps, warp tile 64x32. cp.async 3-stage pipeline.
// Smem stage s (16KB): A @ s*16384, B @ s*16384+8192; swizzle g^=((row>>1)&3).
// MODE 0: row-major fp32 out. MODE 2: QKV fused (z), tf32-rounded scatter
//         to [B,H,S,HD]; Q additionally scaled by 0.125.
// ---------------------------------------------------------------------------
template <int MODE>
__global__ __launch_bounds__(256, 2)
void gemm_tc(const float* __restrict__ A,
             const float* __restrict__ W0, const float* __restrict__ b0_,
             const float* __restrict__ W1, const float* __restrict__ b1_,
             const float* __restrict__ W2, const float* __restrict__ b2_,
             float* __restrict__ C0, float* __restrict__ C1, float* __restrict__ C2)
{
    constexpr int K = 1024;
    constexpr int N = 1024;
    constexpr int NKB = 64;

    const float* W; const float* bias; float* C; int z = 0;
    if (MODE != 2) { W = W0; bias = b0_; C = C0; }
    else {
        z    = blockIdx.z;
        W    = (z == 0) ? W0 : (z == 1) ? W1 : W2;
        bias = (z == 0) ? b0_ : (z == 1) ? b1_ : b2_;
        C    = (z == 0) ? C0 : (z == 1) ? C1 : C2;
    }

    extern __shared__ __align__(16) uint32_t smg[];
    const uint32_t sbase = (uint32_t)__cvta_generic_to_shared(smg);

    const int t    = threadIdx.x;
    const int lane = t & 31;
    const int warp = t >> 5;
    const int gid  = lane >> 2;
    const int tig  = lane & 3;
    const int wm   = warp >> 2;
    const int wn   = warp & 3;
    const int bm   = blockIdx.y * 128;
    const int bn   = blockIdx.x * 128;

    // cp.async staging: thread covers chunks t and t+256 of each 8KB tile
    const int srow = t >> 2;
    const int sg   = t & 3;
    const float* sa0 = A + (size_t)(bm + srow) * K + sg * 4;
    const float* sw0 = W + (size_t)(bn + srow) * K + sg * 4;
    const uint32_t dsw = (uint32_t)(srow * 64 + ((sg ^ ((srow >> 1) & 3)) << 4));

    // ldmatrix fragment addresses (byte offsets within a stage)
    uint32_t relA[4], relB[2];
    {
        const int hiA = (lane >> 4) & 1;
#pragma unroll
        for (int mt = 0; mt < 4; mt++) {
            const int row = wm * 64 + mt * 16 + (lane & 7) + (lane & 8);
            relA[mt] = row * 64 + (uint32_t)((hiA ^ ((row >> 1) & 3)) << 4);
        }
        const int hiB = (lane >> 3) & 1;
#pragma unroll
        for (int n2 = 0; n2 < 2; n2++) {
            const int row = wn * 32 + n2 * 16 + (lane & 7) + ((lane >> 1) & 8);
            relB[n2] = 8192u + row * 64 + (uint32_t)((hiB ^ ((row >> 1) & 3)) << 4);
        }
    }

#define GISSUE(kb, st)                                            \
    {                                                             \
        const uint32_t dd = sbase + (uint32_t)(st) * 16384u + dsw;\
        const float* a = sa0 + (kb) * 16;                         \
        const float* w = sw0 + (kb) * 16;                         \
        cpa16(dd,          a);                                    \
        cpa16(dd + 4096,   a + (size_t)64 * K);                   \
        cpa16(dd + 8192,   w);                                    \
        cpa16(dd + 12288,  w + (size_t)64 * K);                   \
    }

    float acc[4][4][4];
#pragma unroll
    for (int i = 0; i < 4; i++)
#pragma unroll
        for (int j = 0; j < 4; j++)
#pragma unroll
            for (int l = 0; l < 4; l++) acc[i][j][l] = 0.f;

    GISSUE(0, 0); cpcommit();
    GISSUE(1, 1); cpcommit();

    int cs_ = 0, is_ = 2;
    for (int kb = 0; kb < NKB; kb++) {
        cpwait<1>();
        __syncthreads();
        if (kb + 2 < NKB) GISSUE(kb + 2, is_);
        cpcommit();

        const uint32_t sbk = sbase + (uint32_t)cs_ * 16384u;
#pragma unroll
        for (int ks = 0; ks < 2; ks++) {
            const uint32_t kx = (uint32_t)(ks << 5);
            uint4 af[4];
#pragma unroll
            for (int mt = 0; mt < 4; mt++)
                af[mt] = ldsm4(sbk + (relA[mt] ^ kx));
            const uint4 bq0 = ldsm4(sbk + (relB[0] ^ kx));
            const uint4 bq1 = ldsm4(sbk + (relB[1] ^ kx));
#pragma unroll
            for (int mt = 0; mt < 4; mt++) {
                mma8(acc[mt][0], af[mt].x, af[mt].y, af[mt].z, af[mt].w, bq0.x, bq0.y);
                mma8(acc[mt][1], af[mt].x, af[mt].y, af[mt].z, af[mt].w, bq0.z, bq0.w);
                mma8(acc[mt][2], af[mt].x, af[mt].y, af[mt].z, af[mt].w, bq1.x, bq1.y);
                mma8(acc[mt][3], af[mt].x, af[mt].y, af[mt].z, af[mt].w, bq1.z, bq1.w);
            }
        }
        cs_ = (cs_ == 2) ? 0 : cs_ + 1;
        is_ = (is_ == 2) ? 0 : is_ + 1;
    }
#undef GISSUE

    // ---- epilogue ----
    const float qs = (MODE == 2 && z == 0) ? 0.125f : 1.0f;
#pragma unroll
    for (int mt = 0; mt < 4; mt++) {
        const int r1 = bm + wm * 64 + mt * 16 + gid;
        const int r2 = r1 + 8;
#pragma unroll
        for (int nt = 0; nt < 4; nt++) {
            const int n = bn + wn * 32 + nt * 8 + 2 * tig;
            const float bx = __ldg(&bias[n]), by = __ldg(&bias[n + 1]);
            if (MODE == 0) {
                *(float2*)&C[(size_t)r1 * N + n] =
                    make_float2(acc[mt][nt][0] + bx, acc[mt][nt][1] + by);
                *(float2*)&C[(size_t)r2 * N + n] =
                    make_float2(acc[mt][nt][2] + bx, acc[mt][nt][3] + by);
            } else {
                float2 v1 = make_float2(rndtf((acc[mt][nt][0] + bx) * qs),
                                        rndtf((acc[mt][nt][1] + by) * qs));
                float2 v2 = make_float2(rndtf((acc[mt][nt][2] + bx) * qs),
                                        rndtf((acc[mt][nt][3] + by) * qs));
                const int hh = n >> 6, ee = n & 63;
                const int b1r = r1 >> 11, s1r = r1 & (S - 1);
                const int b2r = r2 >> 11, s2r = r2 & (S - 1);
                *(float2*)&C[(((size_t)b1r * H + hh) * S + s1r) * HD + ee] = v1;
                *(float2*)&C[(((size_t)b2r * H + hh) * S + s2r) * HD + ee] = v2;
            }
        }
    }
}

// ---------------------------------------------------------------------------
// TF32 flash attention. Inputs pre-rounded (Q pre-scaled). cp.async
// double-buffered K/V; ldmatrix for Q, K (scores) and P (PV); V scalar LDS.
// Smem bytes: K0 @0, K1 @16384, V0 @32768, V1 @51200, Q @69632, P @86016.
// Total 103424 B. 128 threads; warp owns 16 Q rows.
// ---------------------------------------------------------------------------
__global__ __launch_bounds__(128)
void attn_tc(const float* __restrict__ q,
             const float* __restrict__ k,
             const float* __restrict__ v,
             float* __restrict__ out)
{
    extern __shared__ __align__(16) uint32_t sma[];
    const uint32_t sb = (uint32_t)__cvta_generic_to_shared(sma);

    const int t    = threadIdx.x;
    const int lane = t & 31;
    const int warp = t >> 5;
    const int gid  = lane >> 2;
    const int tig  = lane & 3;
    const int rm   = warp * 16;

    const int hb = blockIdx.y, bb = blockIdx.z;
    const int m0 = blockIdx.x * 64;
    const size_t base = ((size_t)bb * H + hb) * S * HD;
    const float* qb  = q + base + (size_t)m0 * HD;
    const float* kb_ = k + base;
    const float* vb_ = v + base;

    const int crow = t >> 4;   // staging: chunk c = t + i*128 -> row crow+8i, group cg
    const int cg   = t & 15;

    // ---- issue Q (group 0) ----
#pragma unroll
    for (int i = 0; i < 8; i++) {
        const int row = crow + i * 8;
        cpa16(sb + 69632u + row * 256 + (uint32_t)((cg ^ (row & 7)) << 4),
              qb + row * 64 + cg * 4);
    }
    cpcommit();

#define KV_ISSUE(n0, buf)                                                        \
    {                                                                            \
        const float* kp = kb_ + (size_t)(n0) * HD;                               \
        const float* vp = vb_ + (size_t)(n0) * HD;                               \
        _Pragma("unroll")                                                        \
        for (int i = 0; i < 8; i++) {                                            \
            const int row = crow + i * 8;                                        \
            cpa16(sb + (uint32_t)(buf) * 16384u + row * 256 +                    \
                      (uint32_t)((cg ^ (row & 7)) << 4),                         \
                  kp + row * 64 + cg * 4);                                       \
        }                                                                        \
        _Pragma("unroll")                                                        \
        for (int i = 0; i < 8; i++) {                                            \
            const int row = crow + i * 8;                                        \
            cpa16(sb + 32768u + (uint32_t)(buf) * 18432u + row * 288 +           \
                      (uint32_t)(cg << 4),                                       \
                  vp + row * 64 + cg * 4);                                       \
        }                                                                        \
    }

    KV_ISSUE(0, 0);  cpcommit();
    KV_ISSUE(64, 1); cpcommit();

    // ---- fragment addresses ----
    uint32_t relK[4], relQ, relP;
    {
        const int hiB = (lane >> 3) & 1;
#pragma unroll
        for (int n2 = 0; n2 < 4; n2++) {
            const int row = n2 * 16 + (lane & 7) + ((lane >> 1) & 8);
            relK[n2] = row * 256 + (uint32_t)((hiB ^ (row & 7)) << 4);
        }
        const int hiA  = (lane >> 4) & 1;
        const int rowq = rm + (lane & 7) + (lane & 8);
        relQ = 69632u + rowq * 256 + (uint32_t)((hiA ^ (rowq & 7)) << 4);
        relP = 86016u + rowq * 272 + (uint32_t)(hiA << 4);
    }

    cpwait<2>();
    __syncthreads();
    uint4 qf[8];
#pragma unroll
    for (int ks = 0; ks < 8; ks++)
        qf[ks] = ldsm4(sb + (relQ ^ (uint32_t)(ks << 5)));

    float m1 = -1e30f, m2 = -1e30f, l1 = 0.f, l2 = 0.f;
    float o[8][4];
#pragma unroll
    for (int nt = 0; nt < 8; nt++)
#pragma unroll
        for (int j = 0; j < 4; j++) o[nt][j] = 0.f;

    for (int kt = 0; kt < 32; kt++) {
        cpwait<1>();
        __syncthreads();
        const uint32_t kbase = sb + (uint32_t)((kt & 1) << 14);
        const int vw = 8192 + (kt & 1) * 4608;

        // ---- scores = Q . K^T ----
        float sc[8][4];
#pragma unroll
        for (int nt = 0; nt < 8; nt++)
#pragma unroll
            for (int j = 0; j < 4; j++) sc[nt][j] = 0.f;
#pragma unroll
        for (int ks = 0; ks < 8; ks++) {
            const uint32_t kx = (uint32_t)(ks << 5);
#pragma unroll
            for (int n2 = 0; n2 < 4; n2++) {
                const uint4 bf = ldsm4(kbase + (relK[n2] ^ kx));
                mma8(sc[2 * n2],     qf[ks].x, qf[ks].y, qf[ks].z, qf[ks].w, bf.x, bf.y);
                mma8(sc[2 * n2 + 1], qf[ks].x, qf[ks].y, qf[ks].z, qf[ks].w, bf.z, bf.w);
            }
        }

        // ---- online softmax in registers ----
        float mx1 = -1e30f, mx2 = -1e30f;
#pragma unroll
        for (int nt = 0; nt < 8; nt++) {
            mx1 = fmaxf(mx1, fmaxf(sc[nt][0], sc[nt][1]));
            mx2 = fmaxf(mx2, fmaxf(sc[nt][2], sc[nt][3]));
        }
        mx1 = fmaxf(mx1, __shfl_xor_sync(0xffffffffu, mx1, 1));
        mx1 = fmaxf(mx1, __shfl_xor_sync(0xffffffffu, mx1, 2));
        mx2 = fmaxf(mx2, __shfl_xor_sync(0xffffffffu, mx2, 1));
        mx2 = fmaxf(mx2, __shfl_xor_sync(0xffffffffu, mx2, 2));
        const float M1 = fmaxf(m1, mx1);
        const float M2 = fmaxf(m2, mx2);

        float s1 = 0.f, s2 = 0.f;
#pragma unroll
        for (int nt = 0; nt < 8; nt++) {
            sc[nt][0] = __expf(sc[nt][0] - M1); s1 += sc[nt][0];
            sc[nt][1] = __expf(sc[nt][1] - M1); s1 += sc[nt][1];
            sc[nt][2] = __expf(sc[nt][2] - M2); s2 += sc[nt][2];
            sc[nt][3] = __expf(sc[nt][3] - M2); s2 += sc[nt][3];
        }
        s1 += __shfl_xor_sync(0xffffffffu, s1, 1);
        s1 += __shfl_xor_sync(0xffffffffu, s1, 2);
        s2 += __shfl_xor_sync(0xffffffffu, s2, 1);
        s2 += __shfl_xor_sync(0xffffffffu, s2, 2);

        const float c1 = __expf(m1 - M1);
        const float c2 = __expf(m2 - M2);
        l1 = l1 * c1 + s1;
        l2 = l2 * c2 + s2;
        m1 = M1; m2 = M2;
#pragma unroll
        for (int nt = 0; nt < 8; nt++) {
            o[nt][0] *= c1; o[nt][1] *= c1;
            o[nt][2] *= c2; o[nt][3] *= c2;
        }

        // ---- P -> smem (tf32), warp-private rows ----
#pragma unroll
        for (int nt = 0; nt < 8; nt++) {
            const int cc = nt * 8 + 2 * tig;
            *(uint2*)&sma[21504 + (rm + gid) * 68 + cc] =
                make_uint2(f2tf(sc[nt][0]), f2tf(sc[nt][1]));
            *(uint2*)&sma[21504 + (rm + gid + 8) * 68 + cc] =
                make_uint2(f2tf(sc[nt][2]), f2tf(sc[nt][3]));
        }
        __syncwarp();

        // ---- O += P . V ----
#pragma unroll
        for (int ksp = 0; ksp < 8; ksp++) {
            const uint4 pf = ldsm4(sb + relP + (uint32_t)(ksp * 32));
            const int vrow = vw + (ksp * 8 + tig) * 72;
#pragma unroll
            for (int nt = 0; nt < 8; nt++) {
                const uint32_t vb0 = sma[vrow + nt * 8 + gid];
                const uint32_t vb1 = sma[vrow + 288 + nt * 8 + gid];   // +4 rows
                mma8(o[nt], pf.x, pf.y, pf.z, pf.w, vb0, vb1);
            }
        }

        __syncthreads();
        if (kt + 2 < 32) KV_ISSUE((kt + 2) * 64, kt & 1);
        cpcommit();
    }
#undef KV_ISSUE

    // ---- epilogue: normalize, tf32-round, write concat-head layout ----
    const float i1 = 1.f / l1;
    const float i2 = 1.f / l2;
    const int s1r = m0 + rm + gid;
    const int s2r = s1r + 8;
#pragma unroll
    for (int nt = 0; nt < 8; nt++) {
        const int n = nt * 8 + 2 * tig;
        *(float2*)&out[((size_t)bb * S + s1r) * D + hb * HD + n] =
            make_float2(rndtf(o[nt][0] * i1), rndtf(o[nt][1] * i1));
        *(float2*)&out[((size_t)bb * S + s2r) * D + hb * HD + n] =
            make_float2(rndtf(o[nt][2] * i2), rndtf(o[nt][3] * i2));
    }
}

// ---------------------------------------------------------------------------
// Launch
// ---------------------------------------------------------------------------
extern "C" void kernel_launch(void* const* d_in, const int* in_sizes, int n_in,
                              void* d_out, int out_size)
{
    const float* x  = (const float*)d_in[0];
    const float* Wq = (const float*)d_in[1];
    const float* bq = (const float*)d_in[2];
    const float* Wk = (const float*)d_in[3];
    const float* bk = (const float*)d_in[4];
    const float* Wv = (const float*)d_in[5];
    const float* bv = (const float*)d_in[6];
    const float* Wp = (const float*)d_in[7];
    const float* bp = (const float*)d_in[8];
    float* out = (float*)d_out;

    float *q, *k, *v, *attn, *xt, *wt;
    cudaGetSymbolAddress((void**)&q,    g_q);
    cudaGetSymbolAddress((void**)&k,    g_k);
    cudaGetSymbolAddress((void**)&v,    g_v);
    cudaGetSymbolAddress((void**)&attn, g_attn);
    cudaGetSymbolAddress((void**)&xt,   g_xt);
    cudaGetSymbolAddress((void**)&wt,   g_wt);
    float* wqt = wt;
    float* wkt = wt + (size_t)D * D;
    float* wvt = wt + 2 * (size_t)D * D;
    float* wpt = wt + 3 * (size_t)D * D;

    const int smem_gemm = 3 * 16384;   // 49152
    const int smem_attn = 103424;

    cudaFuncSetAttribute(gemm_tc<2>, cudaFuncAttributeMaxDynamicSharedMemorySize, smem_gemm);
    cudaFuncSetAttribute(gemm_tc<0>, cudaFuncAttributeMaxDynamicSharedMemorySize, smem_gemm);
    cudaFuncSetAttribute(attn_tc,    cudaFuncAttributeMaxDynamicSharedMemorySize, smem_attn);

    tf32_cvt<<<dim3(512, 5), 256>>>(x, Wq, Wk, Wv, Wp, xt, wqt, wkt, wvt, wpt);

    gemm_tc<2><<<dim3(D / 128, M / 128, 3), 256, smem_gemm>>>(
        xt, wqt, bq, wkt, bk, wvt, bv, q, k, v);

    attn_tc<<<dim3(S / 64, H, B), 128, smem_attn>>>(q, k, v, attn);

    gemm_tc<0><<<dim3(D / 128, M / 128), 256, smem_gemm>>>(
        attn, wpt, bp, nullptr, nullptr, nullptr, nullptr, out, nullptr, nullptr);
}